// round 7
// baseline (speedup 1.0000x reference)
#include <cuda_runtime.h>

#define TOKS    2048
#define NNODES  1024
#define FEAT    128
#define QUADS   32                 // FEAT/4 float4 lanes per token row
#define NBLK    64
#define CHUNK   32                 // TOKS / NBLK
#define THREADS 1024
#define NGRP    32                 // warps per block

__device__ __forceinline__ float4 f4add(float4 a, float4 b) {
    return make_float4(a.x + b.x, a.y + b.y, a.z + b.z, a.w + b.w);
}

__global__ __launch_bounds__(THREADS, 1)
void span_encoder_kernel(const int* __restrict__ starts,
                         const int* __restrict__ ends,
                         const float4* __restrict__ embed4,
                         float4* __restrict__ out4)
{
    __shared__ __align__(16) float  sdiff[CHUNK][FEAT];  // 16 KB diff array
    __shared__ __align__(16) float4 gaccs[NGRP][QUADS];  // 16 KB per-warp accums
    __shared__ __align__(16) float4 psum[8][QUADS];      //  4 KB 4-warp partials
    __shared__ __align__(16) float4 sred[16][QUADS];     //  8 KB 2-token sums
    __shared__ __align__(16) float4 ssup[4][QUADS];      //  2 KB 8-token sums

    const int tid  = threadIdx.x;
    const int lane = tid & 31;
    const int g    = tid >> 5;               // warp 0..31
    const int q    = lane;                   // float4 lane in feature row
    const int c0   = blockIdx.x * CHUNK;
    const float4 zero4 = make_float4(0.f, 0.f, 0.f, 0.f);

    ((float4*)&sdiff[0][0])[tid] = zero4;    // CHUNK*FEAT/4 == 1024

    // ---- Phase A: classify own node (lane = node) + accumulate ----------
    {
        const int nbase = g * 32;
        int s  = __ldg(&starts[nbase + lane]);
        int e  = __ldg(&ends[nbase + lane]);
        int lo = s - c0;     if (lo < 0)     lo = 0;
        int hi = e - c0 + 1; if (hi > CHUNK) hi = CHUNK;
        bool ov     = (lo < hi);
        bool isFull = ov && (lo == 0) && (hi == CHUNK);

        unsigned mf = __ballot_sync(0xffffffffu, isFull);
        unsigned mp = __ballot_sync(0xffffffffu, ov && !isFull);

        // Full-cover nodes: iterate mask bits, 4 predicated loads in flight
        float4 a0 = zero4, a1 = zero4, a2 = zero4, a3 = zero4;
        unsigned m = mf;
        while (m) {
            int b0 = __ffs(m) - 1;             m &= m - 1;
            int b1 = m ? __ffs(m) - 1 : -1;    if (m) m &= m - 1;
            int b2 = m ? __ffs(m) - 1 : -1;    if (m) m &= m - 1;
            int b3 = m ? __ffs(m) - 1 : -1;    if (m) m &= m - 1;
            a0 = f4add(a0, __ldg(&embed4[(nbase + b0) * QUADS + q]));
            if (b1 >= 0) a1 = f4add(a1, __ldg(&embed4[(nbase + b1) * QUADS + q]));
            if (b2 >= 0) a2 = f4add(a2, __ldg(&embed4[(nbase + b2) * QUADS + q]));
            if (b3 >= 0) a3 = f4add(a3, __ldg(&embed4[(nbase + b3) * QUADS + q]));
        }
        gaccs[g][q] = f4add(f4add(a0, a1), f4add(a2, a3));

        // Partial nodes: broadcast lo/hi from flagging lane, +/- into sdiff
        m = mp;
        while (m) {
            int b   = __ffs(m) - 1;  m &= m - 1;
            int blo = __shfl_sync(0xffffffffu, lo, b);
            int bhi = __shfl_sync(0xffffffffu, hi, b);
            float4 v = __ldg(&embed4[(nbase + b) * QUADS + q]);
            float* d = &sdiff[blo][q * 4];
            atomicAdd(d + 0, v.x);
            atomicAdd(d + 1, v.y);
            atomicAdd(d + 2, v.z);
            atomicAdd(d + 3, v.w);
            if (bhi < CHUNK) {
                float* d2 = &sdiff[bhi][q * 4];
                atomicAdd(d2 + 0, -v.x);
                atomicAdd(d2 + 1, -v.y);
                atomicAdd(d2 + 2, -v.z);
                atomicAdd(d2 + 3, -v.w);
            }
        }
    }
    __syncthreads();

    // ---- Phase B (one parallel phase, role-split warps) -----------------
    if (g < 16) {                            // 2-token slice sums
        sred[g][q] = f4add(((const float4*)sdiff[2 * g])[q],
                           ((const float4*)sdiff[2 * g + 1])[q]);
    } else if (g < 20) {                     // 8-token super sums
        int a = g - 16;
        float4 s0 = f4add(((const float4*)sdiff[8 * a + 0])[q],
                          ((const float4*)sdiff[8 * a + 1])[q]);
        float4 s1 = f4add(((const float4*)sdiff[8 * a + 2])[q],
                          ((const float4*)sdiff[8 * a + 3])[q]);
        float4 s2 = f4add(((const float4*)sdiff[8 * a + 4])[q],
                          ((const float4*)sdiff[8 * a + 5])[q]);
        float4 s3 = f4add(((const float4*)sdiff[8 * a + 6])[q],
                          ((const float4*)sdiff[8 * a + 7])[q]);
        ssup[a][q] = f4add(f4add(s0, s1), f4add(s2, s3));
    } else if (g < 28) {                     // 4-warp accumulator partials
        int a = g - 20;
        float4 s0 = gaccs[4 * a + 0][q];
        float4 s1 = gaccs[4 * a + 1][q];
        float4 s2 = gaccs[4 * a + 2][q];
        float4 s3 = gaccs[4 * a + 3][q];
        psum[a][q] = f4add(f4add(s0, s1), f4add(s2, s3));
    }
    __syncthreads();

    // ---- Phase C: scan, warp g owns token c0+g (psum fold included) -----
    {
        const int a = g >> 3;
        const int b = (g >> 1) & 3;
        const int k = g & 1;
        float4 acc = f4add(f4add(psum[0][q], psum[1][q]),
                           f4add(psum[2][q], psum[3][q]));
        float4 acc2 = f4add(f4add(psum[4][q], psum[5][q]),
                            f4add(psum[6][q], psum[7][q]));
        acc = f4add(acc, acc2);
        #pragma unroll
        for (int s = 0; s < 3; ++s)
            if (s < a) acc = f4add(acc, ssup[s][q]);
        #pragma unroll
        for (int j = 0; j < 3; ++j)
            if (j < b) acc = f4add(acc, sred[4 * a + j][q]);
        if (k) acc = f4add(acc, ((const float4*)sdiff[g - 1])[q]);
        acc = f4add(acc, ((const float4*)sdiff[g])[q]);
        out4[(c0 + g) * QUADS + q] = acc;
    }
}

extern "C" void kernel_launch(void* const* d_in, const int* in_sizes, int n_in,
                              void* d_out, int out_size) {
    const int*    starts = (const int*)d_in[0];
    const int*    ends   = (const int*)d_in[1];
    const float4* embed  = (const float4*)d_in[2];
    float4*       out    = (float4*)d_out;
    (void)in_sizes; (void)n_in; (void)out_size;
    span_encoder_kernel<<<NBLK, THREADS>>>(starts, ends, embed, out);
}

// round 8
// speedup vs baseline: 1.0208x; 1.0208x over previous
#include <cuda_runtime.h>

#define TOKS    2048
#define NNODES  1024
#define FEAT    128
#define QUADS   32                 // FEAT/4 float4 lanes per token row
#define NBLK    64
#define CHUNK   32                 // TOKS / NBLK
#define THREADS 1024
#define NGRP    32                 // warps per block

__device__ __forceinline__ float4 f4add(float4 a, float4 b) {
    return make_float4(a.x + b.x, a.y + b.y, a.z + b.z, a.w + b.w);
}

__global__ __launch_bounds__(THREADS, 1)
void span_encoder_kernel(const int* __restrict__ starts,
                         const int* __restrict__ ends,
                         const float4* __restrict__ embed4,
                         float4* __restrict__ out4)
{
    __shared__ int    s_full[NNODES];                    //  4 KB compact full list
    __shared__ int    s_part[NNODES];                    //  4 KB packed partials
    __shared__ int    s_cnt;                             // nfull | npart<<16
    __shared__ __align__(16) float  sdiff[CHUNK][FEAT];  // 16 KB diff array
    __shared__ __align__(16) float  sfull[FEAT];         // 0.5 KB full-cover sum
    __shared__ __align__(16) float4 sred[16][QUADS];     //  8 KB 2-token sums
    __shared__ __align__(16) float4 ssup[4][QUADS];      //  2 KB 8-token sums

    const int tid  = threadIdx.x;
    const int lane = tid & 31;
    const int g    = tid >> 5;               // warp 0..31
    const int q    = lane;                   // float4 lane in feature row
    const int c0   = blockIdx.x * CHUNK;
    const unsigned lt_mask = (1u << lane) - 1u;
    const float4 zero4 = make_float4(0.f, 0.f, 0.f, 0.f);

    // ---- Issue span loads first; zero smem while they fly ---------------
    int s = __ldg(&starts[tid]);
    int e = __ldg(&ends[tid]);
    if (tid == 0) s_cnt = 0;
    if (tid < FEAT) sfull[tid] = 0.f;
    ((float4*)&sdiff[0][0])[tid] = zero4;    // CHUNK*FEAT/4 == 1024

    // ---- Classify: ballot compaction, single packed counter -------------
    {
        int lo = s - c0;     if (lo < 0)     lo = 0;
        int hi = e - c0 + 1; if (hi > CHUNK) hi = CHUNK;
        bool ov     = (lo < hi);
        bool isFull = ov && (lo == 0) && (hi == CHUNK);
        bool isPart = ov && !isFull;

        unsigned mf = __ballot_sync(0xffffffffu, isFull);
        unsigned mp = __ballot_sync(0xffffffffu, isPart);
        int base = 0;
        if (lane == 0 && (mf | mp))
            base = atomicAdd(&s_cnt, (__popc(mp) << 16) | __popc(mf));
        base = __shfl_sync(0xffffffffu, base, 0);
        if (isFull) s_full[(base & 0xffff) + __popc(mf & lt_mask)] = tid;
        if (isPart) s_part[(base >> 16)   + __popc(mp & lt_mask)]
                        = (tid << 12) | (lo << 6) | hi;
    }
    __syncthreads();

    const int cnt   = s_cnt;
    const int nfull = cnt & 0xffff;
    const int npart = cnt >> 16;

    // ---- Partial nodes first (LDG round overlaps full loop) -------------
    for (int p = g; p < npart; p += NGRP) {
        int pk = s_part[p];
        int n  = pk >> 12;
        int lo = (pk >> 6) & 63;
        int hi = pk & 63;
        float4 v = __ldg(&embed4[n * QUADS + q]);
        float* d = &sdiff[lo][q * 4];
        atomicAdd(d + 0, v.x);
        atomicAdd(d + 1, v.y);
        atomicAdd(d + 2, v.z);
        atomicAdd(d + 3, v.w);
        if (hi < CHUNK) {
            float* d2 = &sdiff[hi][q * 4];
            atomicAdd(d2 + 0, -v.x);
            atomicAdd(d2 + 1, -v.y);
            atomicAdd(d2 + 2, -v.z);
            atomicAdd(d2 + 3, -v.w);
        }
    }

    // ---- Full-cover nodes: uniform strided loop, MLP=4 ------------------
    {
        float4 a0 = zero4, a1 = zero4, a2 = zero4, a3 = zero4;
        int i = g;
        for (; i + 3 * NGRP < nfull; i += 4 * NGRP) {
            int n0 = s_full[i];
            int n1 = s_full[i +     NGRP];
            int n2 = s_full[i + 2 * NGRP];
            int n3 = s_full[i + 3 * NGRP];
            a0 = f4add(a0, __ldg(&embed4[n0 * QUADS + q]));
            a1 = f4add(a1, __ldg(&embed4[n1 * QUADS + q]));
            a2 = f4add(a2, __ldg(&embed4[n2 * QUADS + q]));
            a3 = f4add(a3, __ldg(&embed4[n3 * QUADS + q]));
        }
        for (; i < nfull; i += NGRP)
            a0 = f4add(a0, __ldg(&embed4[s_full[i] * QUADS + q]));

        if (g < nfull) {                     // warp touched >= 1 node
            float4 a = f4add(f4add(a0, a1), f4add(a2, a3));
            float* d = &sfull[q * 4];
            atomicAdd(d + 0, a.x);
            atomicAdd(d + 1, a.y);
            atomicAdd(d + 2, a.z);
            atomicAdd(d + 3, a.w);
        }
    }
    __syncthreads();

    // ---- Phase B: 2-token and 8-token sums (role-split warps) -----------
    if (g < 16) {
        sred[g][q] = f4add(((const float4*)sdiff[2 * g])[q],
                           ((const float4*)sdiff[2 * g + 1])[q]);
    } else if (g < 20) {
        int a = g - 16;
        float4 s0 = f4add(((const float4*)sdiff[8 * a + 0])[q],
                          ((const float4*)sdiff[8 * a + 1])[q]);
        float4 s1 = f4add(((const float4*)sdiff[8 * a + 2])[q],
                          ((const float4*)sdiff[8 * a + 3])[q]);
        float4 s2 = f4add(((const float4*)sdiff[8 * a + 4])[q],
                          ((const float4*)sdiff[8 * a + 5])[q]);
        float4 s3 = f4add(((const float4*)sdiff[8 * a + 6])[q],
                          ((const float4*)sdiff[8 * a + 7])[q]);
        ssup[a][q] = f4add(f4add(s0, s1), f4add(s2, s3));
    }
    __syncthreads();

    // ---- Phase C: scan, warp g owns token c0+g --------------------------
    {
        const int a = g >> 3;
        const int b = (g >> 1) & 3;
        const int k = g & 1;
        float4 acc = ((const float4*)sfull)[q];
        #pragma unroll
        for (int ss = 0; ss < 3; ++ss)
            if (ss < a) acc = f4add(acc, ssup[ss][q]);
        #pragma unroll
        for (int j = 0; j < 3; ++j)
            if (j < b) acc = f4add(acc, sred[4 * a + j][q]);
        if (k) acc = f4add(acc, ((const float4*)sdiff[g - 1])[q]);
        acc = f4add(acc, ((const float4*)sdiff[g])[q]);
        out4[(c0 + g) * QUADS + q] = acc;
    }
}

extern "C" void kernel_launch(void* const* d_in, const int* in_sizes, int n_in,
                              void* d_out, int out_size) {
    const int*    starts = (const int*)d_in[0];
    const int*    ends   = (const int*)d_in[1];
    const float4* embed  = (const float4*)d_in[2];
    float4*       out    = (float4*)d_out;
    (void)in_sizes; (void)n_in; (void)out_size;
    span_encoder_kernel<<<NBLK, THREADS>>>(starts, ends, embed, out);
}

// round 10
// speedup vs baseline: 1.2657x; 1.2399x over previous
#include <cuda_runtime.h>

#define TOKS    2048
#define NNODES  1024
#define FEAT    128
#define QUADS   32                 // float4 per full token row
#define FEATB   64                 // features per block (half)
#define QB      16                 // float4 per row per block
#define NBLK    128                // 64 chunks x 2 feature halves
#define CHUNK   32
#define THREADS 512
#define NGRP    16                 // warps per block

__device__ __forceinline__ float4 f4add(float4 a, float4 b) {
    return make_float4(a.x + b.x, a.y + b.y, a.z + b.z, a.w + b.w);
}

__global__ __launch_bounds__(THREADS, 1)
void span_encoder_kernel(const int* __restrict__ starts,
                         const int* __restrict__ ends,
                         const float4* __restrict__ embed4,
                         float4* __restrict__ out4)
{
    __shared__ int s_full[NNODES];                       //  4 KB
    __shared__ int s_part[NNODES];                       //  4 KB
    __shared__ int s_cnt;                                // nfull | npart<<16
    __shared__ __align__(16) float4 sdiff[CHUNK][QB];    //  8 KB diff array
    __shared__ __align__(16) float4 gaccs[NGRP][QB];     //  4 KB per-warp accums
    __shared__ __align__(16) float4 sfull[QB];           // full-cover total
    __shared__ __align__(16) float4 sred[16][QB];        //  4 KB 2-token sums
    __shared__ __align__(16) float4 ssup[4][QB];         //  1 KB 8-token sums

    const int tid  = threadIdx.x;
    const int lane = tid & 31;
    const int g    = tid >> 5;               // warp 0..15
    const int sub  = lane >> 4;              // node slot 0/1
    const int qq   = lane & 15;              // float4 lane within 64-feat row
    const int c    = blockIdx.x >> 1;
    const int h    = blockIdx.x & 1;         // feature half
    const int c0   = c * CHUNK;
    const int qoff = h * QB;                 // float4 offset into full row
    const unsigned lt_mask = (1u << lane) - 1u;
    const float4 zero4 = make_float4(0.f, 0.f, 0.f, 0.f);

    if (tid == 0) s_cnt = 0;
    ((float4*)&sdiff[0][0])[tid] = zero4;    // CHUNK*QB == 512
    __syncthreads();                         // s_cnt=0 visible BEFORE atomics

    // ---- Classify 1024 nodes (2 rounds), ballot compaction --------------
    #pragma unroll
    for (int r = 0; r < 2; ++r) {
        int n  = r * THREADS + tid;
        int s  = __ldg(&starts[n]);
        int e  = __ldg(&ends[n]);
        int lo = s - c0;     if (lo < 0)     lo = 0;
        int hi = e - c0 + 1; if (hi > CHUNK) hi = CHUNK;
        bool ov     = (lo < hi);
        bool isFull = ov && (lo == 0) && (hi == CHUNK);
        bool isPart = ov && !isFull;

        unsigned mf = __ballot_sync(0xffffffffu, isFull);
        unsigned mp = __ballot_sync(0xffffffffu, isPart);
        int base = 0;
        if (lane == 0 && (mf | mp))
            base = atomicAdd(&s_cnt, (__popc(mp) << 16) | __popc(mf));
        base = __shfl_sync(0xffffffffu, base, 0);
        if (isFull) s_full[(base & 0xffff) + __popc(mf & lt_mask)] = n;
        if (isPart) s_part[(base >> 16)   + __popc(mp & lt_mask)]
                        = (n << 12) | (lo << 6) | hi;
    }
    __syncthreads();

    const int cnt   = s_cnt;
    const int nfull = cnt & 0xffff;
    const int npart = cnt >> 16;

    // ---- Partial nodes: 1 node/warp; sub0 adds at lo, sub1 subs at hi ---
    for (int p = g; p < npart; p += NGRP) {
        int pk = s_part[p];
        int n  = pk >> 12;
        int lo = (pk >> 6) & 63;
        int hi = pk & 63;
        float4 v = __ldg(&embed4[n * QUADS + qoff + qq]);
        if (sub == 0) {
            float* d = &sdiff[lo][qq].x;
            atomicAdd(d + 0, v.x);
            atomicAdd(d + 1, v.y);
            atomicAdd(d + 2, v.z);
            atomicAdd(d + 3, v.w);
        } else if (hi < CHUNK) {
            float* d = &sdiff[hi][qq].x;
            atomicAdd(d + 0, -v.x);
            atomicAdd(d + 1, -v.y);
            atomicAdd(d + 2, -v.z);
            atomicAdd(d + 3, -v.w);
        }
    }

    // ---- Full-cover nodes: 2 nodes/warp/iter, MLP=4 ---------------------
    {
        float4 a0 = zero4, a1 = zero4, a2 = zero4, a3 = zero4;
        int i = g * 2 + sub;                 // 0..31
        for (; i + 96 < nfull; i += 128) {
            int n0 = s_full[i];
            int n1 = s_full[i + 32];
            int n2 = s_full[i + 64];
            int n3 = s_full[i + 96];
            a0 = f4add(a0, __ldg(&embed4[n0 * QUADS + qoff + qq]));
            a1 = f4add(a1, __ldg(&embed4[n1 * QUADS + qoff + qq]));
            a2 = f4add(a2, __ldg(&embed4[n2 * QUADS + qoff + qq]));
            a3 = f4add(a3, __ldg(&embed4[n3 * QUADS + qoff + qq]));
        }
        for (; i < nfull; i += 32)
            a0 = f4add(a0, __ldg(&embed4[s_full[i] * QUADS + qoff + qq]));
        float4 a = f4add(f4add(a0, a1), f4add(a2, a3));
        // fold the two node slots (sub 0/1) across half-warps
        a.x += __shfl_xor_sync(0xffffffffu, a.x, 16);
        a.y += __shfl_xor_sync(0xffffffffu, a.y, 16);
        a.z += __shfl_xor_sync(0xffffffffu, a.z, 16);
        a.w += __shfl_xor_sync(0xffffffffu, a.w, 16);
        if (sub == 0) gaccs[g][qq] = a;
    }
    __syncthreads();

    // ---- Phase B: role-split warps --------------------------------------
    if (g < 8) {                             // 2-token sums: entries 2g+sub
        int sidx = 2 * g + sub;
        sred[sidx][qq] = f4add(sdiff[2 * sidx][qq], sdiff[2 * sidx + 1][qq]);
    } else if (g < 10) {                     // 8-token sums: entries 2(g-8)+sub
        int a = 2 * (g - 8) + sub;
        float4 s0 = f4add(sdiff[8 * a + 0][qq], sdiff[8 * a + 1][qq]);
        float4 s1 = f4add(sdiff[8 * a + 2][qq], sdiff[8 * a + 3][qq]);
        float4 s2 = f4add(sdiff[8 * a + 4][qq], sdiff[8 * a + 5][qq]);
        float4 s3 = f4add(sdiff[8 * a + 6][qq], sdiff[8 * a + 7][qq]);
        ssup[a][qq] = f4add(f4add(s0, s1), f4add(s2, s3));
    } else if (g == 10) {                    // full-cover total: 8-deep + fold
        float4 a = zero4;
        #pragma unroll
        for (int r = 0; r < 8; ++r)
            a = f4add(a, gaccs[8 * sub + r][qq]);
        a.x += __shfl_xor_sync(0xffffffffu, a.x, 16);
        a.y += __shfl_xor_sync(0xffffffffu, a.y, 16);
        a.z += __shfl_xor_sync(0xffffffffu, a.z, 16);
        a.w += __shfl_xor_sync(0xffffffffu, a.w, 16);
        if (sub == 0) sfull[qq] = a;
    }
    __syncthreads();

    // ---- Phase C: scan, warp g owns tokens 2g and 2g+1 ------------------
    {
        const int a = g >> 2;                // 8-token groups before token 2g
        const int b = g & 3;                 // 2-token groups in current one
        float4 acc = sfull[qq];
        #pragma unroll
        for (int ss = 0; ss < 3; ++ss)
            if (ss < a) acc = f4add(acc, ssup[ss][qq]);
        #pragma unroll
        for (int j = 0; j < 3; ++j)
            if (j < b) acc = f4add(acc, sred[4 * a + j][qq]);
        acc = f4add(acc, sdiff[2 * g][qq]);
        out4[(c0 + 2 * g) * QUADS + qoff + qq] = acc;
        acc = f4add(acc, sdiff[2 * g + 1][qq]);
        out4[(c0 + 2 * g + 1) * QUADS + qoff + qq] = acc;
    }
}

extern "C" void kernel_launch(void* const* d_in, const int* in_sizes, int n_in,
                              void* d_out, int out_size) {
    const int*    starts = (const int*)d_in[0];
    const int*    ends   = (const int*)d_in[1];
    const float4* embed  = (const float4*)d_in[2];
    float4*       out    = (float4*)d_out;
    (void)in_sizes; (void)n_in; (void)out_size;
    span_encoder_kernel<<<NBLK, THREADS>>>(starts, ends, embed, out);
}